// round 1
// baseline (speedup 1.0000x reference)
#include <cuda_runtime.h>
#include <cstdint>
#include <cstdio>

#define B_   8
#define C_   768
#define L_   4096
#define NH_  12
#define D_   64
#define BH_  (B_*NH_)
#define PADD 68

// ---------------- scratch (device globals: allocation-free rule) ----------------
__device__ float g_q[(size_t)B_ * C_ * L_];
__device__ float g_k[(size_t)B_ * C_ * L_];
__device__ float g_v[(size_t)B_ * C_ * L_];
__device__ float g_o[(size_t)B_ * C_ * L_];
__device__ float g_beta[(size_t)BH_ * L_];

// ---------------- SGEMM: C[m,n] = sum_k A[(b*C+k)*L + l] * W[k*C + n] ----------------
// A is [B][C][L] (token index l contiguous). Output written in same [B][C][L] layout.
// EPI=0: silu epilogue (projections). EPI=1: add residual R (x) and write final out.
template<int EPI>
__global__ __launch_bounds__(256) void sgemm128(
    const float* __restrict__ A, const float* __restrict__ W,
    const float* __restrict__ R, float* __restrict__ Out)
{
    __shared__ float As[2][8][128];
    __shared__ float Bs[2][8][128];

    const int tid = threadIdx.x;
    const int m0  = blockIdx.x * 128;       // token tile (within one batch: 128 | 4096)
    const int bn  = blockIdx.y * 128;       // out-channel tile
    const int b   = m0 >> 12;
    const int l0  = m0 & 4095;
    const float* Ab = A + (size_t)b * C_ * L_ + l0;

    const int lk  = tid >> 5;               // 0..7   (k row of tile)
    const int lm4 = (tid & 31) << 2;        // 0..124 (float4 within 128)
    const int mt  = tid & 15;               // m group (lanes fastest along m)
    const int nt  = tid >> 4;               // n group

    float acc[8][8];
#pragma unroll
    for (int i = 0; i < 8; i++)
#pragma unroll
        for (int j = 0; j < 8; j++) acc[i][j] = 0.f;

    float4 pa = *(const float4*)(Ab + (size_t)lk * L_ + lm4);
    float4 pb = *(const float4*)(W  + (size_t)lk * C_ + bn + lm4);
    *(float4*)&As[0][lk][lm4] = pa;
    *(float4*)&Bs[0][lk][lm4] = pb;
    __syncthreads();

    for (int k0 = 0; k0 < C_; k0 += 8) {
        const int  buf  = (k0 >> 3) & 1;
        const bool more = (k0 + 8) < C_;
        if (more) {
            pa = *(const float4*)(Ab + (size_t)(k0 + 8 + lk) * L_ + lm4);
            pb = *(const float4*)(W  + (size_t)(k0 + 8 + lk) * C_ + bn + lm4);
        }
#pragma unroll
        for (int kk = 0; kk < 8; kk++) {
            float a[8], bb[8];
            *(float4*)(a)     = *(float4*)&As[buf][kk][mt * 8];
            *(float4*)(a + 4) = *(float4*)&As[buf][kk][mt * 8 + 4];
            *(float4*)(bb)     = *(float4*)&Bs[buf][kk][nt * 8];
            *(float4*)(bb + 4) = *(float4*)&Bs[buf][kk][nt * 8 + 4];
#pragma unroll
            for (int i = 0; i < 8; i++)
#pragma unroll
                for (int j = 0; j < 8; j++) acc[i][j] += a[i] * bb[j];
        }
        if (more) {
            *(float4*)&As[buf ^ 1][lk][lm4] = pa;
            *(float4*)&Bs[buf ^ 1][lk][lm4] = pb;
        }
        __syncthreads();
    }

#pragma unroll
    for (int j = 0; j < 8; j++) {
        const int n = bn + nt * 8 + j;
        float* dst = Out + ((size_t)(b * C_ + n)) * L_ + l0 + mt * 8;
        float v[8];
        if (EPI == 0) {
#pragma unroll
            for (int i = 0; i < 8; i++) {
                float z = acc[i][j];
                v[i] = z / (1.f + __expf(-z));      // silu
            }
        } else {
            const float* r = R + ((size_t)(b * C_ + n)) * L_ + l0 + mt * 8;
#pragma unroll
            for (int i = 0; i < 8; i++) v[i] = acc[i][j] + r[i];
        }
        *(float4*)dst       = *(float4*)v;
        *(float4*)(dst + 4) = *(float4*)(v + 4);
    }
}

// ---------------- beta = sigmoid(t @ Wb), written [B][H][L] ----------------
__global__ __launch_bounds__(256) void beta_kernel(
    const float* __restrict__ X, const float* __restrict__ Wb,
    float* __restrict__ Beta)
{
    __shared__ float As[16][256];
    __shared__ float Ws[16][12];
    const int tid = threadIdx.x;
    const int m0  = blockIdx.x * 256;
    const int b   = m0 >> 12;
    const int l0  = m0 & 4095;
    const float* Ab = X + (size_t)b * C_ * L_ + l0;

    float acc[12];
#pragma unroll
    for (int h = 0; h < 12; h++) acc[h] = 0.f;

    for (int k0 = 0; k0 < C_; k0 += 16) {
#pragma unroll
        for (int kk = 0; kk < 16; kk++) As[kk][tid] = Ab[(size_t)(k0 + kk) * L_ + tid];
        if (tid < 192) Ws[tid / 12][tid % 12] = Wb[(size_t)(k0 + tid / 12) * 12 + (tid % 12)];
        __syncthreads();
#pragma unroll
        for (int kk = 0; kk < 16; kk++) {
            float a = As[kk][tid];
#pragma unroll
            for (int h = 0; h < 12; h++) acc[h] += a * Ws[kk][h];
        }
        __syncthreads();
    }
#pragma unroll
    for (int h = 0; h < 12; h++) {
        Beta[((size_t)(b * NH_ + h)) * L_ + l0 + tid] = 1.f / (1.f + __expf(-acc[h]));
    }
}

// ---------------- delta rule: 1 CTA per (b,h), 64 sequential chunks ----------------
// Fuses l2norm of q,k. All 64x64 matmuls in SMEM with 4x4 register blocking.
__global__ __launch_bounds__(256) void delta_kernel(
    const float* __restrict__ gq, const float* __restrict__ gk,
    const float* __restrict__ gv, const float* __restrict__ gb,
    float* __restrict__ go)
{
    extern __shared__ float sm[];
    float* S   = sm;                 // [d][e]   state
    float* qst = S   + 64 * PADD;    // [d][i]   q transposed (contract-major)
    float* kst = qst + 64 * PADD;    // [d][i]
    float* ks  = kst + 64 * PADD;    // [i][d]   k row-form (for S update)
    float* U   = ks  + 64 * PADD;    // [i][e]   rhs -> solved U
    float* T   = U   + 64 * PADD;    // [i][j]   tri matrix; reused as O staging [e][i]
    float* QKt = T   + 64 * PADD;    // [j][i]   masked q.k (transposed)
    float* bvec = QKt + 64 * PADD;   // [64]

    const int tid = threadIdx.x;
    const int bh  = blockIdx.x;
    const int b   = bh / NH_, h = bh % NH_;
    const size_t base = ((size_t)(b * C_ + h * D_)) * L_;
    const float* qgp = gq + base;
    const float* kgp = gk + base;
    const float* vgp = gv + base;
    const float* bgp = gb + (size_t)bh * L_;
    float* ogp = go + base;

    for (int i = tid; i < 64 * PADD; i += 256) S[i] = 0.f;
    __syncthreads();

    const int ri  = (tid >> 4) << 2;   // output row block
    const int rj  = (tid & 15) << 2;   // output col block
    const int ld  = tid >> 2;          // 0..63 load/store row (d or e)
    const int li0 = (tid & 3) << 4;    // 0,16,32,48

    for (int c = 0; c < 64; c++) {
        const int off = c * 64;
        // ---- load q,k (both layouts), v into U; beta ----
        {
            const float* qrow = qgp + (size_t)ld * L_ + off + li0;
            const float* krow = kgp + (size_t)ld * L_ + off + li0;
            const float* vrow = vgp + (size_t)ld * L_ + off + li0;
#pragma unroll
            for (int u = 0; u < 16; u += 4) {
                float4 qv = *(const float4*)(qrow + u);
                float4 kv = *(const float4*)(krow + u);
                float4 vv = *(const float4*)(vrow + u);
                *(float4*)&qst[ld * PADD + li0 + u] = qv;
                *(float4*)&kst[ld * PADD + li0 + u] = kv;
                ks[(li0 + u + 0) * PADD + ld] = kv.x;
                ks[(li0 + u + 1) * PADD + ld] = kv.y;
                ks[(li0 + u + 2) * PADD + ld] = kv.z;
                ks[(li0 + u + 3) * PADD + ld] = kv.w;
                U[(li0 + u + 0) * PADD + ld] = vv.x;
                U[(li0 + u + 1) * PADD + ld] = vv.y;
                U[(li0 + u + 2) * PADD + ld] = vv.z;
                U[(li0 + u + 3) * PADD + ld] = vv.w;
            }
            if (tid < 64) bvec[tid] = bgp[off + tid];
        }
        __syncthreads();
        // ---- l2norm q,k per token (over d) ----
        {
            const int tok = tid >> 2;
            const int d0  = (tid & 3) << 4;
            float sq = 0.f, sk = 0.f;
#pragma unroll
            for (int d = d0; d < d0 + 16; d++) {
                float qv = qst[d * PADD + tok]; sq += qv * qv;
                float kv = kst[d * PADD + tok]; sk += kv * kv;
            }
            sq += __shfl_xor_sync(0xFFFFFFFFu, sq, 1);
            sq += __shfl_xor_sync(0xFFFFFFFFu, sq, 2);
            sk += __shfl_xor_sync(0xFFFFFFFFu, sk, 1);
            sk += __shfl_xor_sync(0xFFFFFFFFu, sk, 2);
            const float rq = rsqrtf(sq + 1e-6f);
            const float rk = rsqrtf(sk + 1e-6f);
#pragma unroll
            for (int d = d0; d < d0 + 16; d++) {
                qst[d * PADD + tok] *= rq;
                kst[d * PADD + tok] *= rk;
                ks[tok * PADD + d]  *= rk;
            }
        }
        __syncthreads();
        // ---- T = I + strict_tril(b * K K^T); QKt[j][i] = (j<=i)? q_i.k_j : 0;
        //      U  = b * (V - K S)  (fused: same A operand kst) ----
        {
            float aT[4][4], aQ[4][4], aU[4][4];
#pragma unroll
            for (int u = 0; u < 4; u++)
#pragma unroll
                for (int w = 0; w < 4; w++) { aT[u][w] = 0.f; aQ[u][w] = 0.f; aU[u][w] = 0.f; }
            for (int d = 0; d < 64; d++) {
                float4 a4 = *(float4*)&kst[d * PADD + ri];
                float4 b1 = *(float4*)&kst[d * PADD + rj];
                float4 b2 = *(float4*)&qst[d * PADD + rj];
                float4 b3 = *(float4*)&S[d * PADD + rj];
                float av[4]  = {a4.x, a4.y, a4.z, a4.w};
                float b1v[4] = {b1.x, b1.y, b1.z, b1.w};
                float b2v[4] = {b2.x, b2.y, b2.z, b2.w};
                float b3v[4] = {b3.x, b3.y, b3.z, b3.w};
#pragma unroll
                for (int u = 0; u < 4; u++)
#pragma unroll
                    for (int w = 0; w < 4; w++) {
                        aT[u][w] += av[u] * b1v[w];
                        aQ[u][w] += av[u] * b2v[w];
                        aU[u][w] += av[u] * b3v[w];
                    }
            }
#pragma unroll
            for (int u = 0; u < 4; u++) {
                const int gi = ri + u;
#pragma unroll
                for (int w = 0; w < 4; w++) {
                    const int gj = rj + w;
                    T[gi * PADD + gj]   = (gj < gi) ? bvec[gi] * aT[u][w] : (gi == gj ? 1.f : 0.f);
                    QKt[gi * PADD + gj] = (gi <= gj) ? aQ[u][w] : 0.f;
                    const int idx = gi * PADD + gj;
                    U[idx] = bvec[gi] * (U[idx] - aU[u][w]);
                }
            }
        }
        __syncthreads();
        // ---- forward substitution: (unit-lower T) U = rhs, per-column serial ----
        if (tid < 64) {
            const int e = tid;
            for (int i = 1; i < 64; i++) {
                const float* Trow = &T[i * PADD];
                float s0 = 0.f, s1 = 0.f, s2 = 0.f, s3 = 0.f;
                int j = 0;
                for (; j + 4 <= i; j += 4) {
                    s0 += Trow[j]     * U[(j)     * PADD + e];
                    s1 += Trow[j + 1] * U[(j + 1) * PADD + e];
                    s2 += Trow[j + 2] * U[(j + 2) * PADD + e];
                    s3 += Trow[j + 3] * U[(j + 3) * PADD + e];
                }
                for (; j < i; j++) s0 += Trow[j] * U[j * PADD + e];
                U[i * PADD + e] -= (s0 + s1) + (s2 + s3);
            }
        }
        __syncthreads();
        // ---- O = Q S + masked(QK) U  -> staged transposed into T as O[e][i] ----
        {
            float aO[4][4];
#pragma unroll
            for (int u = 0; u < 4; u++)
#pragma unroll
                for (int w = 0; w < 4; w++) aO[u][w] = 0.f;
            for (int d = 0; d < 64; d++) {
                float4 a4 = *(float4*)&qst[d * PADD + ri];
                float4 b4 = *(float4*)&S[d * PADD + rj];
                float av[4] = {a4.x, a4.y, a4.z, a4.w};
                float bv[4] = {b4.x, b4.y, b4.z, b4.w};
#pragma unroll
                for (int u = 0; u < 4; u++)
#pragma unroll
                    for (int w = 0; w < 4; w++) aO[u][w] += av[u] * bv[w];
            }
            for (int j2 = 0; j2 < 64; j2++) {
                float4 a4 = *(float4*)&QKt[j2 * PADD + ri];
                float4 b4 = *(float4*)&U[j2 * PADD + rj];
                float av[4] = {a4.x, a4.y, a4.z, a4.w};
                float bv[4] = {b4.x, b4.y, b4.z, b4.w};
#pragma unroll
                for (int u = 0; u < 4; u++)
#pragma unroll
                    for (int w = 0; w < 4; w++) aO[u][w] += av[u] * bv[w];
            }
#pragma unroll
            for (int u = 0; u < 4; u++)
#pragma unroll
                for (int w = 0; w < 4; w++)
                    T[(rj + w) * PADD + (ri + u)] = aO[u][w];   // O staged [e][i]
        }
        __syncthreads();
        // ---- S += K^T U ; write O chunk to global ----
        {
            float aS[4][4];
#pragma unroll
            for (int u = 0; u < 4; u++)
#pragma unroll
                for (int w = 0; w < 4; w++) aS[u][w] = 0.f;
            for (int i2 = 0; i2 < 64; i2++) {
                float4 a4 = *(float4*)&ks[i2 * PADD + ri];   // k[i2][d=ri..]
                float4 b4 = *(float4*)&U[i2 * PADD + rj];
                float av[4] = {a4.x, a4.y, a4.z, a4.w};
                float bv[4] = {b4.x, b4.y, b4.z, b4.w};
#pragma unroll
                for (int u = 0; u < 4; u++)
#pragma unroll
                    for (int w = 0; w < 4; w++) aS[u][w] += av[u] * bv[w];
            }
#pragma unroll
            for (int u = 0; u < 4; u++)
#pragma unroll
                for (int w = 0; w < 4; w++)
                    S[(ri + u) * PADD + rj + w] += aS[u][w];

            float* dst = ogp + (size_t)ld * L_ + off + li0;
#pragma unroll
            for (int u = 0; u < 16; u += 4)
                *(float4*)(dst + u) = *(float4*)&T[ld * PADD + li0 + u];
        }
        __syncthreads();
    }
}

// ---------------- launch ----------------
extern "C" void kernel_launch(void* const* d_in, const int* in_sizes, int n_in,
                              void* d_out, int out_size)
{
    const float* x  = (const float*)d_in[0];
    const float* Wq = (const float*)d_in[1];
    const float* Wk = (const float*)d_in[2];
    const float* Wv = (const float*)d_in[3];
    const float* Wb = (const float*)d_in[4];
    const float* Wo = (const float*)d_in[5];
    float* out = (float*)d_out;

    float *qp, *kp, *vp, *op, *bp;
    cudaGetSymbolAddress((void**)&qp, g_q);
    cudaGetSymbolAddress((void**)&kp, g_k);
    cudaGetSymbolAddress((void**)&vp, g_v);
    cudaGetSymbolAddress((void**)&op, g_o);
    cudaGetSymbolAddress((void**)&bp, g_beta);

    const int smemDelta = (7 * 64 * PADD + 64) * (int)sizeof(float);
    cudaFuncSetAttribute(delta_kernel, cudaFuncAttributeMaxDynamicSharedMemorySize, smemDelta);

    dim3 grid(256, 6), blk(256);
    sgemm128<0><<<grid, blk>>>(x, Wq, nullptr, qp);
    sgemm128<0><<<grid, blk>>>(x, Wk, nullptr, kp);
    sgemm128<0><<<grid, blk>>>(x, Wv, nullptr, vp);
    beta_kernel<<<128, 256>>>(x, Wb, bp);
    delta_kernel<<<96, 256, smemDelta>>>(qp, kp, vp, bp, op);
    sgemm128<1><<<grid, blk>>>(op, Wo, x, out);
}

// round 2
// speedup vs baseline: 1.5979x; 1.5979x over previous
#include <cuda_runtime.h>
#include <cstdint>
#include <cstdio>

#define B_   8
#define C_   768
#define L_   4096
#define NH_  12
#define D_   64
#define BH_  (B_*NH_)
#define PADD 68
#define SPAD 136

// ---------------- scratch (device globals: allocation-free rule) ----------------
__device__ float g_q[(size_t)B_ * C_ * L_];
__device__ float g_k[(size_t)B_ * C_ * L_];
__device__ float g_v[(size_t)B_ * C_ * L_];
__device__ float g_o[(size_t)B_ * C_ * L_];
__device__ float g_beta[(size_t)BH_ * L_];

__device__ __forceinline__ uint32_t f2tf(float f) {
    uint32_t r;
    asm("cvt.rna.tf32.f32 %0, %1;" : "=r"(r) : "f"(f));
    return r;
}

__device__ __forceinline__ void mma_tf32(float c[4], const uint32_t a[4], const uint32_t b[2]) {
    asm volatile(
        "mma.sync.aligned.m16n8k8.row.col.f32.tf32.tf32.f32 "
        "{%0,%1,%2,%3}, {%4,%5,%6,%7}, {%8,%9}, {%0,%1,%2,%3};"
        : "+f"(c[0]), "+f"(c[1]), "+f"(c[2]), "+f"(c[3])
        : "r"(a[0]), "r"(a[1]), "r"(a[2]), "r"(a[3]), "r"(b[0]), "r"(b[1]));
}

// ---------------- tf32 tensor-core GEMM ----------------
// Computes Out[(b*C+n)*L + l] = epi( sum_k A[(b*C+k)*L + l] * W[k*C + n] )
// A is [B][C][L] (l contiguous). CTA tile 128(l) x 128(n). 8 warps, warp tile 32x64.
// EPI=0: silu. EPI=1: add residual R, final output.
// NZ=3: blockIdx.z selects (W0->O0, W1->O1, W2->O2). NZ=1: W0->O0 only.
template<int EPI, int NZ>
__global__ __launch_bounds__(256) void gemm_tf32(
    const float* __restrict__ A,
    const float* __restrict__ W0, const float* __restrict__ W1, const float* __restrict__ W2,
    const float* __restrict__ R,
    float* __restrict__ O0, float* __restrict__ O1, float* __restrict__ O2)
{
    __shared__ uint32_t As[2][16][SPAD];
    __shared__ uint32_t Bs[2][16][SPAD];

    const int tid  = threadIdx.x;
    const int wid  = tid >> 5;
    const int lane = tid & 31;
    const int m0   = blockIdx.x * 128;
    const int b    = m0 >> 12;
    const int l0   = m0 & 4095;
    const int n0   = blockIdx.y * 128;

    const float* W;
    float* Out;
    if (NZ == 3) {
        const int z = blockIdx.z;
        W   = (z == 0) ? W0 : (z == 1) ? W1 : W2;
        Out = (z == 0) ? O0 : (z == 1) ? O1 : O2;
    } else {
        W = W0; Out = O0;
    }
    const float* Ab = A + (size_t)b * C_ * L_ + l0;

    // global loader indices: 16 rows x 128 cols, 2 float4 per thread
    const int lk = tid >> 5;               // 0..7 (+8 second pass)
    const int lc = (tid & 31) << 2;        // 0..124

    // warp tile
    const int wm = (wid & 3) * 32;
    const int wn = (wid >> 2) * 64;
    const int g  = lane >> 2;
    const int tg = lane & 3;

    float acc[2][8][4];
#pragma unroll
    for (int mf = 0; mf < 2; mf++)
#pragma unroll
        for (int j = 0; j < 8; j++)
#pragma unroll
            for (int r = 0; r < 4; r++) acc[mf][j][r] = 0.f;

    float4 pa0, pa1, pw0, pw1;
    pa0 = *(const float4*)(Ab + (size_t)lk * L_ + lc);
    pa1 = *(const float4*)(Ab + (size_t)(lk + 8) * L_ + lc);
    pw0 = *(const float4*)(W + (size_t)lk * C_ + n0 + lc);
    pw1 = *(const float4*)(W + (size_t)(lk + 8) * C_ + n0 + lc);
    {
        uint32_t* d0 = &As[0][lk][lc];
        uint32_t* d1 = &As[0][lk + 8][lc];
        d0[0] = f2tf(pa0.x); d0[1] = f2tf(pa0.y); d0[2] = f2tf(pa0.z); d0[3] = f2tf(pa0.w);
        d1[0] = f2tf(pa1.x); d1[1] = f2tf(pa1.y); d1[2] = f2tf(pa1.z); d1[3] = f2tf(pa1.w);
        uint32_t* e0 = &Bs[0][lk][lc];
        uint32_t* e1 = &Bs[0][lk + 8][lc];
        e0[0] = f2tf(pw0.x); e0[1] = f2tf(pw0.y); e0[2] = f2tf(pw0.z); e0[3] = f2tf(pw0.w);
        e1[0] = f2tf(pw1.x); e1[1] = f2tf(pw1.y); e1[2] = f2tf(pw1.z); e1[3] = f2tf(pw1.w);
    }
    __syncthreads();

    for (int k0 = 0; k0 < C_; k0 += 16) {
        const int  buf  = (k0 >> 4) & 1;
        const bool more = (k0 + 16) < C_;
        if (more) {
            pa0 = *(const float4*)(Ab + (size_t)(k0 + 16 + lk) * L_ + lc);
            pa1 = *(const float4*)(Ab + (size_t)(k0 + 24 + lk) * L_ + lc);
            pw0 = *(const float4*)(W + (size_t)(k0 + 16 + lk) * C_ + n0 + lc);
            pw1 = *(const float4*)(W + (size_t)(k0 + 24 + lk) * C_ + n0 + lc);
        }
#pragma unroll
        for (int ks = 0; ks < 16; ks += 8) {
            uint32_t af[2][4], bf[8][2];
#pragma unroll
            for (int mf = 0; mf < 2; mf++) {
                const int mr = wm + mf * 16 + g;
                af[mf][0] = As[buf][ks + tg][mr];
                af[mf][1] = As[buf][ks + tg][mr + 8];
                af[mf][2] = As[buf][ks + 4 + tg][mr];
                af[mf][3] = As[buf][ks + 4 + tg][mr + 8];
            }
#pragma unroll
            for (int j = 0; j < 8; j++) {
                const int nc = wn + j * 8 + g;
                bf[j][0] = Bs[buf][ks + tg][nc];
                bf[j][1] = Bs[buf][ks + 4 + tg][nc];
            }
#pragma unroll
            for (int mf = 0; mf < 2; mf++)
#pragma unroll
                for (int j = 0; j < 8; j++)
                    mma_tf32(acc[mf][j], af[mf], bf[j]);
        }
        if (more) {
            uint32_t* d0 = &As[buf ^ 1][lk][lc];
            uint32_t* d1 = &As[buf ^ 1][lk + 8][lc];
            d0[0] = f2tf(pa0.x); d0[1] = f2tf(pa0.y); d0[2] = f2tf(pa0.z); d0[3] = f2tf(pa0.w);
            d1[0] = f2tf(pa1.x); d1[1] = f2tf(pa1.y); d1[2] = f2tf(pa1.z); d1[3] = f2tf(pa1.w);
            uint32_t* e0 = &Bs[buf ^ 1][lk][lc];
            uint32_t* e1 = &Bs[buf ^ 1][lk + 8][lc];
            e0[0] = f2tf(pw0.x); e0[1] = f2tf(pw0.y); e0[2] = f2tf(pw0.z); e0[3] = f2tf(pw0.w);
            e1[0] = f2tf(pw1.x); e1[1] = f2tf(pw1.y); e1[2] = f2tf(pw1.z); e1[3] = f2tf(pw1.w);
        }
        __syncthreads();
    }

    // ---- epilogue: stage 32-n slices through smem, coalesced channel-major stores ----
    float* stage = (float*)&As[0][0][0];   // 32 x 132 floats, fits in As/Bs union
#pragma unroll 1
    for (int s = 0; s < 4; s++) {
#pragma unroll
        for (int mf = 0; mf < 2; mf++)
#pragma unroll
            for (int j = 0; j < 8; j++) {
                if (((wn + j * 8) >> 5) != s) continue;
                const int n = (wn + j * 8 + tg * 2) & 31;
                const int m = wm + mf * 16 + g;
                float v0 = acc[mf][j][0], v1 = acc[mf][j][1];
                float v2 = acc[mf][j][2], v3 = acc[mf][j][3];
                if (EPI == 0) {
                    v0 = v0 / (1.f + __expf(-v0));
                    v1 = v1 / (1.f + __expf(-v1));
                    v2 = v2 / (1.f + __expf(-v2));
                    v3 = v3 / (1.f + __expf(-v3));
                }
                stage[n * 132 + m]           = v0;
                stage[(n + 1) * 132 + m]     = v1;
                stage[n * 132 + m + 8]       = v2;
                stage[(n + 1) * 132 + m + 8] = v3;
            }
        __syncthreads();
        {
            const int nr   = tid >> 3;            // 0..31
            const int lcol = (tid & 7) << 4;      // 0..112
            const size_t gb = ((size_t)(b * C_ + n0 + s * 32 + nr)) * L_ + l0 + lcol;
            float v[16];
#pragma unroll
            for (int t = 0; t < 16; t++) v[t] = stage[nr * 132 + lcol + t];
            if (EPI == 1) {
                const float* r = R + gb;
#pragma unroll
                for (int t = 0; t < 16; t++) v[t] += r[t];
            }
            float* dst = Out + gb;
            *(float4*)(dst)      = *(float4*)(v);
            *(float4*)(dst + 4)  = *(float4*)(v + 4);
            *(float4*)(dst + 8)  = *(float4*)(v + 8);
            *(float4*)(dst + 12) = *(float4*)(v + 12);
        }
        __syncthreads();
    }
}

// ---------------- beta = sigmoid(t @ Wb), written [B][H][L] ----------------
__global__ __launch_bounds__(256) void beta_kernel(
    const float* __restrict__ X, const float* __restrict__ Wb,
    float* __restrict__ Beta)
{
    __shared__ float As[16][256];
    __shared__ float Ws[16][12];
    const int tid = threadIdx.x;
    const int m0  = blockIdx.x * 256;
    const int b   = m0 >> 12;
    const int l0  = m0 & 4095;
    const float* Ab = X + (size_t)b * C_ * L_ + l0;

    float acc[12];
#pragma unroll
    for (int h = 0; h < 12; h++) acc[h] = 0.f;

    for (int k0 = 0; k0 < C_; k0 += 16) {
#pragma unroll
        for (int kk = 0; kk < 16; kk++) As[kk][tid] = Ab[(size_t)(k0 + kk) * L_ + tid];
        if (tid < 192) Ws[tid / 12][tid % 12] = Wb[(size_t)(k0 + tid / 12) * 12 + (tid % 12)];
        __syncthreads();
#pragma unroll
        for (int kk = 0; kk < 16; kk++) {
            float a = As[kk][tid];
#pragma unroll
            for (int h = 0; h < 12; h++) acc[h] += a * Ws[kk][h];
        }
        __syncthreads();
    }
#pragma unroll
    for (int h = 0; h < 12; h++) {
        Beta[((size_t)(b * NH_ + h)) * L_ + l0 + tid] = 1.f / (1.f + __expf(-acc[h]));
    }
}

// ---------------- delta rule: 1 CTA per (b,h), 64 sequential chunks ----------------
__global__ __launch_bounds__(256) void delta_kernel(
    const float* __restrict__ gq, const float* __restrict__ gk,
    const float* __restrict__ gv, const float* __restrict__ gb,
    float* __restrict__ go)
{
    extern __shared__ float sm[];
    float* S   = sm;                 // [d][e]   state
    float* qst = S   + 64 * PADD;    // [d][i]   q transposed (contract-major)
    float* kst = qst + 64 * PADD;    // [d][i]
    float* ks  = kst + 64 * PADD;    // [i][d]   k row-form (for S update)
    float* U   = ks  + 64 * PADD;    // [i][e]   rhs -> solved U
    float* T   = U   + 64 * PADD;    // [i][j]   tri matrix; reused as O staging [e][i]
    float* QKt = T   + 64 * PADD;    // [j][i]   masked q.k (transposed)
    float* bvec = QKt + 64 * PADD;   // [64]

    const int tid = threadIdx.x;
    const int bh  = blockIdx.x;
    const int b   = bh / NH_, h = bh % NH_;
    const size_t base = ((size_t)(b * C_ + h * D_)) * L_;
    const float* qgp = gq + base;
    const float* kgp = gk + base;
    const float* vgp = gv + base;
    const float* bgp = gb + (size_t)bh * L_;
    float* ogp = go + base;

    for (int i = tid; i < 64 * PADD; i += 256) S[i] = 0.f;
    __syncthreads();

    const int ri  = (tid >> 4) << 2;
    const int rj  = (tid & 15) << 2;
    const int ld  = tid >> 2;
    const int li0 = (tid & 3) << 4;

    for (int c = 0; c < 64; c++) {
        const int off = c * 64;
        {
            const float* qrow = qgp + (size_t)ld * L_ + off + li0;
            const float* krow = kgp + (size_t)ld * L_ + off + li0;
            const float* vrow = vgp + (size_t)ld * L_ + off + li0;
#pragma unroll
            for (int u = 0; u < 16; u += 4) {
                float4 qv = *(const float4*)(qrow + u);
                float4 kv = *(const float4*)(krow + u);
                float4 vv = *(const float4*)(vrow + u);
                *(float4*)&qst[ld * PADD + li0 + u] = qv;
                *(float4*)&kst[ld * PADD + li0 + u] = kv;
                ks[(li0 + u + 0) * PADD + ld] = kv.x;
                ks[(li0 + u + 1) * PADD + ld] = kv.y;
                ks[(li0 + u + 2) * PADD + ld] = kv.z;
                ks[(li0 + u + 3) * PADD + ld] = kv.w;
                U[(li0 + u + 0) * PADD + ld] = vv.x;
                U[(li0 + u + 1) * PADD + ld] = vv.y;
                U[(li0 + u + 2) * PADD + ld] = vv.z;
                U[(li0 + u + 3) * PADD + ld] = vv.w;
            }
            if (tid < 64) bvec[tid] = bgp[off + tid];
        }
        __syncthreads();
        {
            const int tok = tid >> 2;
            const int d0  = (tid & 3) << 4;
            float sq = 0.f, sk = 0.f;
#pragma unroll
            for (int d = d0; d < d0 + 16; d++) {
                float qv = qst[d * PADD + tok]; sq += qv * qv;
                float kv = kst[d * PADD + tok]; sk += kv * kv;
            }
            sq += __shfl_xor_sync(0xFFFFFFFFu, sq, 1);
            sq += __shfl_xor_sync(0xFFFFFFFFu, sq, 2);
            sk += __shfl_xor_sync(0xFFFFFFFFu, sk, 1);
            sk += __shfl_xor_sync(0xFFFFFFFFu, sk, 2);
            const float rq = rsqrtf(sq + 1e-6f);
            const float rk = rsqrtf(sk + 1e-6f);
#pragma unroll
            for (int d = d0; d < d0 + 16; d++) {
                qst[d * PADD + tok] *= rq;
                kst[d * PADD + tok] *= rk;
                ks[tok * PADD + d]  *= rk;
            }
        }
        __syncthreads();
        {
            float aT[4][4], aQ[4][4], aU[4][4];
#pragma unroll
            for (int u = 0; u < 4; u++)
#pragma unroll
                for (int w = 0; w < 4; w++) { aT[u][w] = 0.f; aQ[u][w] = 0.f; aU[u][w] = 0.f; }
            for (int d = 0; d < 64; d++) {
                float4 a4 = *(float4*)&kst[d * PADD + ri];
                float4 b1 = *(float4*)&kst[d * PADD + rj];
                float4 b2 = *(float4*)&qst[d * PADD + rj];
                float4 b3 = *(float4*)&S[d * PADD + rj];
                float av[4]  = {a4.x, a4.y, a4.z, a4.w};
                float b1v[4] = {b1.x, b1.y, b1.z, b1.w};
                float b2v[4] = {b2.x, b2.y, b2.z, b2.w};
                float b3v[4] = {b3.x, b3.y, b3.z, b3.w};
#pragma unroll
                for (int u = 0; u < 4; u++)
#pragma unroll
                    for (int w = 0; w < 4; w++) {
                        aT[u][w] += av[u] * b1v[w];
                        aQ[u][w] += av[u] * b2v[w];
                        aU[u][w] += av[u] * b3v[w];
                    }
            }
#pragma unroll
            for (int u = 0; u < 4; u++) {
                const int gi = ri + u;
#pragma unroll
                for (int w = 0; w < 4; w++) {
                    const int gj = rj + w;
                    T[gi * PADD + gj]   = (gj < gi) ? bvec[gi] * aT[u][w] : (gi == gj ? 1.f : 0.f);
                    QKt[gi * PADD + gj] = (gi <= gj) ? aQ[u][w] : 0.f;
                    const int idx = gi * PADD + gj;
                    U[idx] = bvec[gi] * (U[idx] - aU[u][w]);
                }
            }
        }
        __syncthreads();
        if (tid < 64) {
            const int e = tid;
            for (int i = 1; i < 64; i++) {
                const float* Trow = &T[i * PADD];
                float s0 = 0.f, s1 = 0.f, s2 = 0.f, s3 = 0.f;
                int j = 0;
                for (; j + 4 <= i; j += 4) {
                    s0 += Trow[j]     * U[(j)     * PADD + e];
                    s1 += Trow[j + 1] * U[(j + 1) * PADD + e];
                    s2 += Trow[j + 2] * U[(j + 2) * PADD + e];
                    s3 += Trow[j + 3] * U[(j + 3) * PADD + e];
                }
                for (; j < i; j++) s0 += Trow[j] * U[j * PADD + e];
                U[i * PADD + e] -= (s0 + s1) + (s2 + s3);
            }
        }
        __syncthreads();
        {
            float aO[4][4];
#pragma unroll
            for (int u = 0; u < 4; u++)
#pragma unroll
                for (int w = 0; w < 4; w++) aO[u][w] = 0.f;
            for (int d = 0; d < 64; d++) {
                float4 a4 = *(float4*)&qst[d * PADD + ri];
                float4 b4 = *(float4*)&S[d * PADD + rj];
                float av[4] = {a4.x, a4.y, a4.z, a4.w};
                float bv[4] = {b4.x, b4.y, b4.z, b4.w};
#pragma unroll
                for (int u = 0; u < 4; u++)
#pragma unroll
                    for (int w = 0; w < 4; w++) aO[u][w] += av[u] * bv[w];
            }
            for (int j2 = 0; j2 < 64; j2++) {
                float4 a4 = *(float4*)&QKt[j2 * PADD + ri];
                float4 b4 = *(float4*)&U[j2 * PADD + rj];
                float av[4] = {a4.x, a4.y, a4.z, a4.w};
                float bv[4] = {b4.x, b4.y, b4.z, b4.w};
#pragma unroll
                for (int u = 0; u < 4; u++)
#pragma unroll
                    for (int w = 0; w < 4; w++) aO[u][w] += av[u] * bv[w];
            }
#pragma unroll
            for (int u = 0; u < 4; u++)
#pragma unroll
                for (int w = 0; w < 4; w++)
                    T[(rj + w) * PADD + (ri + u)] = aO[u][w];
        }
        __syncthreads();
        {
            float aS[4][4];
#pragma unroll
            for (int u = 0; u < 4; u++)
#pragma unroll
                for (int w = 0; w < 4; w++) aS[u][w] = 0.f;
            for (int i2 = 0; i2 < 64; i2++) {
                float4 a4 = *(float4*)&ks[i2 * PADD + ri];
                float4 b4 = *(float4*)&U[i2 * PADD + rj];
                float av[4] = {a4.x, a4.y, a4.z, a4.w};
                float bv[4] = {b4.x, b4.y, b4.z, b4.w};
#pragma unroll
                for (int u = 0; u < 4; u++)
#pragma unroll
                    for (int w = 0; w < 4; w++) aS[u][w] += av[u] * bv[w];
            }
#pragma unroll
            for (int u = 0; u < 4; u++)
#pragma unroll
                for (int w = 0; w < 4; w++)
                    S[(ri + u) * PADD + rj + w] += aS[u][w];

            float* dst = ogp + (size_t)ld * L_ + off + li0;
#pragma unroll
            for (int u = 0; u < 16; u += 4)
                *(float4*)(dst + u) = *(float4*)&T[ld * PADD + li0 + u];
        }
        __syncthreads();
    }
}

// ---------------- launch ----------------
extern "C" void kernel_launch(void* const* d_in, const int* in_sizes, int n_in,
                              void* d_out, int out_size)
{
    const float* x  = (const float*)d_in[0];
    const float* Wq = (const float*)d_in[1];
    const float* Wk = (const float*)d_in[2];
    const float* Wv = (const float*)d_in[3];
    const float* Wb = (const float*)d_in[4];
    const float* Wo = (const float*)d_in[5];
    float* out = (float*)d_out;

    float *qp, *kp, *vp, *op, *bp;
    cudaGetSymbolAddress((void**)&qp, g_q);
    cudaGetSymbolAddress((void**)&kp, g_k);
    cudaGetSymbolAddress((void**)&vp, g_v);
    cudaGetSymbolAddress((void**)&op, g_o);
    cudaGetSymbolAddress((void**)&bp, g_beta);

    const int smemDelta = (7 * 64 * PADD + 64) * (int)sizeof(float);
    cudaFuncSetAttribute(delta_kernel, cudaFuncAttributeMaxDynamicSharedMemorySize, smemDelta);

    dim3 blk(256);
    // beta first so the fixed ncu capture (-s 5) lands on the qkv tf32 GEMM
    beta_kernel<<<128, blk>>>(x, Wb, bp);
    gemm_tf32<0, 3><<<dim3(256, 6, 3), blk>>>(x, Wq, Wk, Wv, nullptr, qp, kp, vp);
    delta_kernel<<<96, blk, smemDelta>>>(qp, kp, vp, bp, op);
    gemm_tf32<1, 1><<<dim3(256, 6, 1), blk>>>(op, Wo, nullptr, nullptr, x, out, nullptr, nullptr);
}